// round 1
// baseline (speedup 1.0000x reference)
#include <cuda_runtime.h>
#include <math.h>
#include <stdint.h>

// ---------------- Model constants ----------------
#define B_      2
#define SEQ     2048
#define INDIM   64
#define DMODEL  512
#define NH      8
#define DK      64
#define NL      2
#define BSROWS  (B_ * SEQ)        // 4096
#define KTOP    204               // max(1, SEQ/10)
#define LNEPS   1e-5f

// ---------------- Scratch (static device memory; no allocs) ----------------
__device__ float g_h [BSROWS * DMODEL];
__device__ float g_q [BSROWS * DMODEL];
__device__ float g_k [BSROWS * DMODEL];
__device__ float g_v [BSROWS * DMODEL];
__device__ float g_ao[BSROWS * DMODEL];
__device__ float g_fc[BSROWS * DMODEL];
__device__ float g_sc[(size_t)B_ * NH * SEQ * SEQ];   // 268 MB score scratch

// ---------------- helpers ----------------
__device__ __forceinline__ unsigned f2k(float f) {
    unsigned u = __float_as_uint(f);
    return (u & 0x80000000u) ? ~u : (u | 0x80000000u);
}
__device__ __forceinline__ float k2f(unsigned k) {
    return __uint_as_float((k & 0x80000000u) ? (k & 0x7FFFFFFFu) : ~k);
}

__device__ __forceinline__ float block_reduce_sum(float v, float* red) {
    // 256 threads
    #pragma unroll
    for (int o = 16; o > 0; o >>= 1) v += __shfl_down_sync(0xffffffffu, v, o);
    if ((threadIdx.x & 31) == 0) red[threadIdx.x >> 5] = v;
    __syncthreads();
    if (threadIdx.x < 8) {
        v = red[threadIdx.x];
        #pragma unroll
        for (int o = 4; o > 0; o >>= 1) v += __shfl_down_sync(0xffu, v, o);
        if (threadIdx.x == 0) red[0] = v;
    }
    __syncthreads();
    float r = red[0];
    __syncthreads();
    return r;
}

__device__ __forceinline__ float block_reduce_max(float v, float* red) {
    #pragma unroll
    for (int o = 16; o > 0; o >>= 1) v = fmaxf(v, __shfl_down_sync(0xffffffffu, v, o));
    if ((threadIdx.x & 31) == 0) red[threadIdx.x >> 5] = v;
    __syncthreads();
    if (threadIdx.x < 8) {
        v = red[threadIdx.x];
        #pragma unroll
        for (int o = 4; o > 0; o >>= 1) v = fmaxf(v, __shfl_down_sync(0xffu, v, o));
        if (threadIdx.x == 0) red[0] = v;
    }
    __syncthreads();
    float r = red[0];
    __syncthreads();
    return r;
}

// ---------------- Generic tiled SGEMM: C = A[MxK] @ W[KxN] + bias ----------------
// Requires M%64==0, N%64==0, K%32==0. Row-major, packed strides.
#define TM 64
#define TN 64
#define BKP 32

__global__ __launch_bounds__(256) void gemm_nn_bias(
    const float* __restrict__ A, const float* __restrict__ W,
    const float* __restrict__ bias, float* __restrict__ C,
    int M, int N, int K)
{
    __shared__ float As[TM][BKP + 1];
    __shared__ float Ws[BKP][TN];
    const int tid = threadIdx.x;
    const int tx = tid & 15, ty = tid >> 4;
    const int row0 = blockIdx.y * TM;
    const int col0 = blockIdx.x * TN;

    float acc[4][4] = {};

    for (int k0 = 0; k0 < K; k0 += BKP) {
        #pragma unroll
        for (int i = tid; i < TM * BKP; i += 256) {
            int r = i >> 5, c = i & 31;
            As[r][c] = A[(size_t)(row0 + r) * K + k0 + c];
        }
        #pragma unroll
        for (int i = tid; i < BKP * TN; i += 256) {
            int r = i >> 6, c = i & 63;
            Ws[r][c] = W[(size_t)(k0 + r) * N + col0 + c];
        }
        __syncthreads();
        #pragma unroll
        for (int kk = 0; kk < BKP; kk++) {
            float a[4], bb[4];
            #pragma unroll
            for (int i = 0; i < 4; i++) a[i] = As[ty * 4 + i][kk];
            #pragma unroll
            for (int j = 0; j < 4; j++) bb[j] = Ws[kk][tx * 4 + j];
            #pragma unroll
            for (int i = 0; i < 4; i++)
                #pragma unroll
                for (int j = 0; j < 4; j++)
                    acc[i][j] = fmaf(a[i], bb[j], acc[i][j]);
        }
        __syncthreads();
    }
    #pragma unroll
    for (int i = 0; i < 4; i++) {
        #pragma unroll
        for (int j = 0; j < 4; j++) {
            int c = col0 + tx * 4 + j;
            C[(size_t)(row0 + ty * 4 + i) * N + c] = acc[i][j] + bias[c];
        }
    }
}

// ---------------- QK^T scores: S[bh,q,k] = 0.125 * Q[b,q,h,:] . K[b,k,h,:] ----------------
__global__ __launch_bounds__(256) void qk_scores_kernel()
{
    const int bh = blockIdx.z;
    const int b = bh >> 3, h = bh & 7;
    const float* Qb = g_q + (size_t)b * SEQ * DMODEL + h * DK;
    const float* Kb = g_k + (size_t)b * SEQ * DMODEL + h * DK;
    float* Sb = g_sc + (size_t)bh * SEQ * SEQ;
    const int q0 = blockIdx.y * 64, k0 = blockIdx.x * 64;

    __shared__ float Qs[64][DK + 1];
    __shared__ float Ks[64][DK + 1];
    const int tid = threadIdx.x;
    const int tx = tid & 15, ty = tid >> 4;

    for (int i = tid; i < 64 * DK; i += 256) {
        int r = i >> 6, c = i & 63;
        Qs[r][c] = Qb[(size_t)(q0 + r) * DMODEL + c];
        Ks[r][c] = Kb[(size_t)(k0 + r) * DMODEL + c];
    }
    __syncthreads();

    float acc[4][4] = {};
    #pragma unroll 8
    for (int kk = 0; kk < DK; kk++) {
        float a[4], bb[4];
        #pragma unroll
        for (int i = 0; i < 4; i++) a[i] = Qs[ty * 4 + i][kk];
        #pragma unroll
        for (int j = 0; j < 4; j++) bb[j] = Ks[tx * 4 + j][kk];
        #pragma unroll
        for (int i = 0; i < 4; i++)
            #pragma unroll
            for (int j = 0; j < 4; j++)
                acc[i][j] = fmaf(a[i], bb[j], acc[i][j]);
    }
    #pragma unroll
    for (int i = 0; i < 4; i++)
        #pragma unroll
        for (int j = 0; j < 4; j++)
            Sb[(size_t)(q0 + ty * 4 + i) * SEQ + k0 + tx * 4 + j] = acc[i][j] * 0.125f;
}

// ---------------- per-row top-k threshold (exact k-th largest) + masked softmax ----------------
__global__ __launch_bounds__(256) void topk_softmax_kernel()
{
    float* s = g_sc + (size_t)blockIdx.x * SEQ;
    __shared__ float sv[SEQ];
    __shared__ unsigned hist[256];
    __shared__ unsigned sh_pfx;
    __shared__ int sh_k;
    __shared__ float red[32];
    const int tid = threadIdx.x;

    #pragma unroll
    for (int i = tid; i < SEQ; i += 256) sv[i] = s[i];
    if (tid == 0) { sh_pfx = 0u; sh_k = KTOP; }
    __syncthreads();

    // 4-pass MSB radix select of the k-th largest key
    #pragma unroll
    for (int pass = 0; pass < 4; pass++) {
        const int shift = 24 - 8 * pass;
        hist[tid & 255] = 0;            // 256 threads zero 256 bins
        __syncthreads();
        const unsigned pfx = sh_pfx;
        const unsigned hmask = (pass == 0) ? 0u : (0xFFFFFFFFu << (shift + 8));
        for (int i = tid; i < SEQ; i += 256) {
            unsigned key = f2k(sv[i]);
            if ((key & hmask) == pfx)
                atomicAdd(&hist[(key >> shift) & 255u], 1u);
        }
        __syncthreads();
        if (tid == 0) {
            int kk = sh_k;
            int bsel = 255;
            for (;; bsel--) {
                int c = (int)hist[bsel];
                if (kk <= c || bsel == 0) break;
                kk -= c;
            }
            sh_k = kk;
            sh_pfx = pfx | ((unsigned)bsel << shift);
        }
        __syncthreads();
    }
    const float thr = k2f(sh_pfx);

    // row max (max element is always kept)
    float m = -INFINITY;
    for (int i = tid; i < SEQ; i += 256) m = fmaxf(m, sv[i]);
    m = block_reduce_max(m, red);

    float sum = 0.f;
    for (int i = tid; i < SEQ; i += 256)
        if (sv[i] >= thr) sum += __expf(sv[i] - m);
    sum = block_reduce_sum(sum, red);
    const float inv = 1.0f / sum;

    for (int i = tid; i < SEQ; i += 256)
        s[i] = (sv[i] >= thr) ? __expf(sv[i] - m) * inv : 0.f;
}

// ---------------- attn @ V:  O[b,q,h*64+d] = sum_k P[bh,q,k] * V[b,k,h*64+d] ----------------
__global__ __launch_bounds__(256) void av_kernel()
{
    const int bh = blockIdx.y;
    const int b = bh >> 3, h = bh & 7;
    const float* Pb = g_sc + (size_t)bh * SEQ * SEQ;
    const float* Vb = g_v + (size_t)b * SEQ * DMODEL + h * DK;
    float* Ob = g_ao + (size_t)b * SEQ * DMODEL + h * DK;
    const int q0 = blockIdx.x * 64;

    __shared__ float Ps[64][65];
    __shared__ float Vs[64][65];
    const int tid = threadIdx.x;
    const int tx = tid & 15, ty = tid >> 4;

    float acc[4][4] = {};
    for (int k0 = 0; k0 < SEQ; k0 += 64) {
        for (int i = tid; i < 64 * 64; i += 256) {
            int r = i >> 6, c = i & 63;
            Ps[r][c] = Pb[(size_t)(q0 + r) * SEQ + k0 + c];
            Vs[r][c] = Vb[(size_t)(k0 + r) * DMODEL + c];
        }
        __syncthreads();
        #pragma unroll 8
        for (int kk = 0; kk < 64; kk++) {
            float a[4], bb[4];
            #pragma unroll
            for (int i = 0; i < 4; i++) a[i] = Ps[ty * 4 + i][kk];
            #pragma unroll
            for (int j = 0; j < 4; j++) bb[j] = Vs[kk][tx * 4 + j];
            #pragma unroll
            for (int i = 0; i < 4; i++)
                #pragma unroll
                for (int j = 0; j < 4; j++)
                    acc[i][j] = fmaf(a[i], bb[j], acc[i][j]);
        }
        __syncthreads();
    }
    #pragma unroll
    for (int i = 0; i < 4; i++)
        #pragma unroll
        for (int j = 0; j < 4; j++)
            Ob[(size_t)(q0 + ty * 4 + i) * DMODEL + tx * 4 + j] = acc[i][j];
}

// ---------------- residual + layernorm (in-place on g_h): h = LN(h + fc) ----------------
__global__ __launch_bounds__(256) void add_ln_kernel(const float* __restrict__ gamma,
                                                     const float* __restrict__ beta)
{
    const int row = blockIdx.x;
    float* hr = g_h + (size_t)row * DMODEL;
    const float* fr = g_fc + (size_t)row * DMODEL;
    __shared__ float vals[DMODEL];
    __shared__ float red[32];
    const int tid = threadIdx.x;

    float lsum = 0.f;
    #pragma unroll
    for (int i = tid; i < DMODEL; i += 256) {
        float v = hr[i] + fr[i];
        vals[i] = v;
        lsum += v;
    }
    const float mu = block_reduce_sum(lsum, red) * (1.0f / DMODEL);

    float lvar = 0.f;
    #pragma unroll
    for (int i = tid; i < DMODEL; i += 256) {
        float d = vals[i] - mu;
        lvar += d * d;
    }
    const float var = block_reduce_sum(lvar, red) * (1.0f / DMODEL);
    const float rs = rsqrtf(var + LNEPS);

    #pragma unroll
    for (int i = tid; i < DMODEL; i += 256)
        hr[i] = (vals[i] - mu) * rs * gamma[i] + beta[i];
}

// ---------------- decoder: out[b, n] = h[b, SEQ-1, :] . dec_W[:, n] + dec_b[n] ----------------
__global__ void decoder_kernel(const float* __restrict__ dW,
                               const float* __restrict__ db,
                               float* __restrict__ out)
{
    const int b = blockIdx.x;
    const int n = threadIdx.x;   // 64
    const float* hr = g_h + ((size_t)b * SEQ + (SEQ - 1)) * DMODEL;
    float acc = db[n];
    #pragma unroll 8
    for (int d = 0; d < DMODEL; d++)
        acc = fmaf(hr[d], dW[d * INDIM + n], acc);
    out[(size_t)b * INDIM + n] = acc;
}

// ---------------- host launcher ----------------
extern "C" void kernel_launch(void* const* d_in, const int* in_sizes, int n_in,
                              void* d_out, int out_size)
{
    const float* x     = (const float*)d_in[0];
    const float* enc_W = (const float*)d_in[1];
    const float* enc_b = (const float*)d_in[2];
    const float* Wq    = (const float*)d_in[3];
    const float* bq    = (const float*)d_in[4];
    const float* Wk    = (const float*)d_in[5];
    const float* bk    = (const float*)d_in[6];
    const float* Wv    = (const float*)d_in[7];
    const float* bv    = (const float*)d_in[8];
    const float* fcW   = (const float*)d_in[9];
    const float* fcb   = (const float*)d_in[10];
    const float* ln_g  = (const float*)d_in[11];
    const float* ln_b  = (const float*)d_in[12];
    const float* dec_W = (const float*)d_in[13];
    const float* dec_b = (const float*)d_in[14];
    float* out = (float*)d_out;

    float *p_h, *p_q, *p_k, *p_v, *p_ao, *p_fc;
    cudaGetSymbolAddress((void**)&p_h,  g_h);
    cudaGetSymbolAddress((void**)&p_q,  g_q);
    cudaGetSymbolAddress((void**)&p_k,  g_k);
    cudaGetSymbolAddress((void**)&p_v,  g_v);
    cudaGetSymbolAddress((void**)&p_ao, g_ao);
    cudaGetSymbolAddress((void**)&p_fc, g_fc);

    const dim3 gProj(DMODEL / TN, BSROWS / TM);   // (8, 64)

    // encoder: h = x @ enc_W + enc_b   (K = 64)
    gemm_nn_bias<<<gProj, 256>>>(x, enc_W, enc_b, p_h, BSROWS, DMODEL, INDIM);

    for (int l = 0; l < NL; l++) {
        const size_t wofs = (size_t)l * DMODEL * DMODEL;
        const size_t bofs = (size_t)l * DMODEL;

        gemm_nn_bias<<<gProj, 256>>>(p_h, Wq + wofs, bq + bofs, p_q, BSROWS, DMODEL, DMODEL);
        gemm_nn_bias<<<gProj, 256>>>(p_h, Wk + wofs, bk + bofs, p_k, BSROWS, DMODEL, DMODEL);
        gemm_nn_bias<<<gProj, 256>>>(p_h, Wv + wofs, bv + bofs, p_v, BSROWS, DMODEL, DMODEL);

        qk_scores_kernel<<<dim3(SEQ / 64, SEQ / 64, B_ * NH), 256>>>();
        topk_softmax_kernel<<<B_ * NH * SEQ, 256>>>();
        av_kernel<<<dim3(SEQ / 64, B_ * NH), 256>>>();

        gemm_nn_bias<<<gProj, 256>>>(p_ao, fcW + wofs, fcb + bofs, p_fc, BSROWS, DMODEL, DMODEL);
        add_ln_kernel<<<BSROWS, 256>>>(ln_g + bofs, ln_b + bofs);
    }

    decoder_kernel<<<B_, INDIM>>>(dec_W, dec_b, out);
}

// round 2
// speedup vs baseline: 1.0013x; 1.0013x over previous
#include <cuda_runtime.h>
#include <math.h>
#include <stdint.h>

// ---------------- Model constants ----------------
#define B_      2
#define SEQ     2048
#define INDIM   64
#define DMODEL  512
#define NH      8
#define DK      64
#define NL      2
#define BSROWS  (B_ * SEQ)        // 4096
#define KTOP    204               // max(1, SEQ/10)
#define LNEPS   1e-5f

// ---------------- Scratch (static device memory; no allocs) ----------------
__device__ float g_h [BSROWS * DMODEL];
__device__ float g_q [BSROWS * DMODEL];
__device__ float g_k [BSROWS * DMODEL];
__device__ float g_v [BSROWS * DMODEL];
__device__ float g_ao[BSROWS * DMODEL];
__device__ float g_fc[BSROWS * DMODEL];
__device__ float g_sc[(size_t)B_ * NH * SEQ * SEQ];   // 268 MB score scratch

// ---------------- helpers ----------------
__device__ __forceinline__ unsigned f2k(float f) {
    unsigned u = __float_as_uint(f);
    return (u & 0x80000000u) ? ~u : (u | 0x80000000u);
}
__device__ __forceinline__ float k2f(unsigned k) {
    return __uint_as_float((k & 0x80000000u) ? (k & 0x7FFFFFFFu) : ~k);
}

__device__ __forceinline__ float block_reduce_sum(float v, float* red) {
    // 256 threads
    #pragma unroll
    for (int o = 16; o > 0; o >>= 1) v += __shfl_down_sync(0xffffffffu, v, o);
    if ((threadIdx.x & 31) == 0) red[threadIdx.x >> 5] = v;
    __syncthreads();
    if (threadIdx.x < 8) {
        v = red[threadIdx.x];
        #pragma unroll
        for (int o = 4; o > 0; o >>= 1) v += __shfl_down_sync(0xffu, v, o);
        if (threadIdx.x == 0) red[0] = v;
    }
    __syncthreads();
    float r = red[0];
    __syncthreads();
    return r;
}

__device__ __forceinline__ float block_reduce_max(float v, float* red) {
    #pragma unroll
    for (int o = 16; o > 0; o >>= 1) v = fmaxf(v, __shfl_down_sync(0xffffffffu, v, o));
    if ((threadIdx.x & 31) == 0) red[threadIdx.x >> 5] = v;
    __syncthreads();
    if (threadIdx.x < 8) {
        v = red[threadIdx.x];
        #pragma unroll
        for (int o = 4; o > 0; o >>= 1) v = fmaxf(v, __shfl_down_sync(0xffu, v, o));
        if (threadIdx.x == 0) red[0] = v;
    }
    __syncthreads();
    float r = red[0];
    __syncthreads();
    return r;
}

// ---------------- Generic tiled SGEMM: C = A[MxK] @ W[KxN] + bias ----------------
// Requires M%64==0, N%64==0, K%32==0. Row-major, packed strides.
#define TM 64
#define TN 64
#define BKP 32

__global__ __launch_bounds__(256) void gemm_nn_bias(
    const float* __restrict__ A, const float* __restrict__ W,
    const float* __restrict__ bias, float* __restrict__ C,
    int M, int N, int K)
{
    __shared__ float As[TM][BKP + 1];
    __shared__ float Ws[BKP][TN];
    const int tid = threadIdx.x;
    const int tx = tid & 15, ty = tid >> 4;
    const int row0 = blockIdx.y * TM;
    const int col0 = blockIdx.x * TN;

    float acc[4][4] = {};

    for (int k0 = 0; k0 < K; k0 += BKP) {
        #pragma unroll
        for (int i = tid; i < TM * BKP; i += 256) {
            int r = i >> 5, c = i & 31;
            As[r][c] = A[(size_t)(row0 + r) * K + k0 + c];
        }
        #pragma unroll
        for (int i = tid; i < BKP * TN; i += 256) {
            int r = i >> 6, c = i & 63;
            Ws[r][c] = W[(size_t)(k0 + r) * N + col0 + c];
        }
        __syncthreads();
        #pragma unroll
        for (int kk = 0; kk < BKP; kk++) {
            float a[4], bb[4];
            #pragma unroll
            for (int i = 0; i < 4; i++) a[i] = As[ty * 4 + i][kk];
            #pragma unroll
            for (int j = 0; j < 4; j++) bb[j] = Ws[kk][tx * 4 + j];
            #pragma unroll
            for (int i = 0; i < 4; i++)
                #pragma unroll
                for (int j = 0; j < 4; j++)
                    acc[i][j] = fmaf(a[i], bb[j], acc[i][j]);
        }
        __syncthreads();
    }
    #pragma unroll
    for (int i = 0; i < 4; i++) {
        #pragma unroll
        for (int j = 0; j < 4; j++) {
            int c = col0 + tx * 4 + j;
            C[(size_t)(row0 + ty * 4 + i) * N + c] = acc[i][j] + bias[c];
        }
    }
}

// ---------------- QK^T scores: S[bh,q,k] = 0.125 * Q[b,q,h,:] . K[b,k,h,:] ----------------
__global__ __launch_bounds__(256) void qk_scores_kernel()
{
    const int bh = blockIdx.z;
    const int b = bh >> 3, h = bh & 7;
    const float* Qb = g_q + (size_t)b * SEQ * DMODEL + h * DK;
    const float* Kb = g_k + (size_t)b * SEQ * DMODEL + h * DK;
    float* Sb = g_sc + (size_t)bh * SEQ * SEQ;
    const int q0 = blockIdx.y * 64, k0 = blockIdx.x * 64;

    __shared__ float Qs[64][DK + 1];
    __shared__ float Ks[64][DK + 1];
    const int tid = threadIdx.x;
    const int tx = tid & 15, ty = tid >> 4;

    for (int i = tid; i < 64 * DK; i += 256) {
        int r = i >> 6, c = i & 63;
        Qs[r][c] = Qb[(size_t)(q0 + r) * DMODEL + c];
        Ks[r][c] = Kb[(size_t)(k0 + r) * DMODEL + c];
    }
    __syncthreads();

    float acc[4][4] = {};
    #pragma unroll 8
    for (int kk = 0; kk < DK; kk++) {
        float a[4], bb[4];
        #pragma unroll
        for (int i = 0; i < 4; i++) a[i] = Qs[ty * 4 + i][kk];
        #pragma unroll
        for (int j = 0; j < 4; j++) bb[j] = Ks[tx * 4 + j][kk];
        #pragma unroll
        for (int i = 0; i < 4; i++)
            #pragma unroll
            for (int j = 0; j < 4; j++)
                acc[i][j] = fmaf(a[i], bb[j], acc[i][j]);
    }
    #pragma unroll
    for (int i = 0; i < 4; i++)
        #pragma unroll
        for (int j = 0; j < 4; j++)
            Sb[(size_t)(q0 + ty * 4 + i) * SEQ + k0 + tx * 4 + j] = acc[i][j] * 0.125f;
}

// ---------------- per-row top-k threshold (exact k-th largest) + masked softmax ----------------
__global__ __launch_bounds__(256) void topk_softmax_kernel()
{
    float* s = g_sc + (size_t)blockIdx.x * SEQ;
    __shared__ float sv[SEQ];
    __shared__ unsigned hist[256];
    __shared__ unsigned sh_pfx;
    __shared__ int sh_k;
    __shared__ float red[32];
    const int tid = threadIdx.x;

    #pragma unroll
    for (int i = tid; i < SEQ; i += 256) sv[i] = s[i];
    if (tid == 0) { sh_pfx = 0u; sh_k = KTOP; }
    __syncthreads();

    // 4-pass MSB radix select of the k-th largest key
    #pragma unroll
    for (int pass = 0; pass < 4; pass++) {
        const int shift = 24 - 8 * pass;
        hist[tid & 255] = 0;            // 256 threads zero 256 bins
        __syncthreads();
        const unsigned pfx = sh_pfx;
        const unsigned hmask = (pass == 0) ? 0u : (0xFFFFFFFFu << (shift + 8));
        for (int i = tid; i < SEQ; i += 256) {
            unsigned key = f2k(sv[i]);
            if ((key & hmask) == pfx)
                atomicAdd(&hist[(key >> shift) & 255u], 1u);
        }
        __syncthreads();
        if (tid == 0) {
            int kk = sh_k;
            int bsel = 255;
            for (;; bsel--) {
                int c = (int)hist[bsel];
                if (kk <= c || bsel == 0) break;
                kk -= c;
            }
            sh_k = kk;
            sh_pfx = pfx | ((unsigned)bsel << shift);
        }
        __syncthreads();
    }
    const float thr = k2f(sh_pfx);

    // row max (max element is always kept)
    float m = -INFINITY;
    for (int i = tid; i < SEQ; i += 256) m = fmaxf(m, sv[i]);
    m = block_reduce_max(m, red);

    float sum = 0.f;
    for (int i = tid; i < SEQ; i += 256)
        if (sv[i] >= thr) sum += __expf(sv[i] - m);
    sum = block_reduce_sum(sum, red);
    const float inv = 1.0f / sum;

    for (int i = tid; i < SEQ; i += 256)
        s[i] = (sv[i] >= thr) ? __expf(sv[i] - m) * inv : 0.f;
}

// ---------------- attn @ V:  O[b,q,h*64+d] = sum_k P[bh,q,k] * V[b,k,h*64+d] ----------------
__global__ __launch_bounds__(256) void av_kernel()
{
    const int bh = blockIdx.y;
    const int b = bh >> 3, h = bh & 7;
    const float* Pb = g_sc + (size_t)bh * SEQ * SEQ;
    const float* Vb = g_v + (size_t)b * SEQ * DMODEL + h * DK;
    float* Ob = g_ao + (size_t)b * SEQ * DMODEL + h * DK;
    const int q0 = blockIdx.x * 64;

    __shared__ float Ps[64][65];
    __shared__ float Vs[64][65];
    const int tid = threadIdx.x;
    const int tx = tid & 15, ty = tid >> 4;

    float acc[4][4] = {};
    for (int k0 = 0; k0 < SEQ; k0 += 64) {
        for (int i = tid; i < 64 * 64; i += 256) {
            int r = i >> 6, c = i & 63;
            Ps[r][c] = Pb[(size_t)(q0 + r) * SEQ + k0 + c];
            Vs[r][c] = Vb[(size_t)(k0 + r) * DMODEL + c];
        }
        __syncthreads();
        #pragma unroll 8
        for (int kk = 0; kk < 64; kk++) {
            float a[4], bb[4];
            #pragma unroll
            for (int i = 0; i < 4; i++) a[i] = Ps[ty * 4 + i][kk];
            #pragma unroll
            for (int j = 0; j < 4; j++) bb[j] = Vs[kk][tx * 4 + j];
            #pragma unroll
            for (int i = 0; i < 4; i++)
                #pragma unroll
                for (int j = 0; j < 4; j++)
                    acc[i][j] = fmaf(a[i], bb[j], acc[i][j]);
        }
        __syncthreads();
    }
    #pragma unroll
    for (int i = 0; i < 4; i++)
        #pragma unroll
        for (int j = 0; j < 4; j++)
            Ob[(size_t)(q0 + ty * 4 + i) * DMODEL + tx * 4 + j] = acc[i][j];
}

// ---------------- residual + layernorm (in-place on g_h): h = LN(h + fc) ----------------
__global__ __launch_bounds__(256) void add_ln_kernel(const float* __restrict__ gamma,
                                                     const float* __restrict__ beta)
{
    const int row = blockIdx.x;
    float* hr = g_h + (size_t)row * DMODEL;
    const float* fr = g_fc + (size_t)row * DMODEL;
    __shared__ float vals[DMODEL];
    __shared__ float red[32];
    const int tid = threadIdx.x;

    float lsum = 0.f;
    #pragma unroll
    for (int i = tid; i < DMODEL; i += 256) {
        float v = hr[i] + fr[i];
        vals[i] = v;
        lsum += v;
    }
    const float mu = block_reduce_sum(lsum, red) * (1.0f / DMODEL);

    float lvar = 0.f;
    #pragma unroll
    for (int i = tid; i < DMODEL; i += 256) {
        float d = vals[i] - mu;
        lvar += d * d;
    }
    const float var = block_reduce_sum(lvar, red) * (1.0f / DMODEL);
    const float rs = rsqrtf(var + LNEPS);

    #pragma unroll
    for (int i = tid; i < DMODEL; i += 256)
        hr[i] = (vals[i] - mu) * rs * gamma[i] + beta[i];
}

// ---------------- decoder: out[b, n] = h[b, SEQ-1, :] . dec_W[:, n] + dec_b[n] ----------------
__global__ void decoder_kernel(const float* __restrict__ dW,
                               const float* __restrict__ db,
                               float* __restrict__ out)
{
    const int b = blockIdx.x;
    const int n = threadIdx.x;   // 64
    const float* hr = g_h + ((size_t)b * SEQ + (SEQ - 1)) * DMODEL;
    float acc = db[n];
    #pragma unroll 8
    for (int d = 0; d < DMODEL; d++)
        acc = fmaf(hr[d], dW[d * INDIM + n], acc);
    out[(size_t)b * INDIM + n] = acc;
}

// ---------------- host launcher ----------------
extern "C" void kernel_launch(void* const* d_in, const int* in_sizes, int n_in,
                              void* d_out, int out_size)
{
    const float* x     = (const float*)d_in[0];
    const float* enc_W = (const float*)d_in[1];
    const float* enc_b = (const float*)d_in[2];
    const float* Wq    = (const float*)d_in[3];
    const float* bq    = (const float*)d_in[4];
    const float* Wk    = (const float*)d_in[5];
    const float* bk    = (const float*)d_in[6];
    const float* Wv    = (const float*)d_in[7];
    const float* bv    = (const float*)d_in[8];
    const float* fcW   = (const float*)d_in[9];
    const float* fcb   = (const float*)d_in[10];
    const float* ln_g  = (const float*)d_in[11];
    const float* ln_b  = (const float*)d_in[12];
    const float* dec_W = (const float*)d_in[13];
    const float* dec_b = (const float*)d_in[14];
    float* out = (float*)d_out;

    float *p_h, *p_q, *p_k, *p_v, *p_ao, *p_fc;
    cudaGetSymbolAddress((void**)&p_h,  g_h);
    cudaGetSymbolAddress((void**)&p_q,  g_q);
    cudaGetSymbolAddress((void**)&p_k,  g_k);
    cudaGetSymbolAddress((void**)&p_v,  g_v);
    cudaGetSymbolAddress((void**)&p_ao, g_ao);
    cudaGetSymbolAddress((void**)&p_fc, g_fc);

    const dim3 gProj(DMODEL / TN, BSROWS / TM);   // (8, 64)

    // encoder: h = x @ enc_W + enc_b   (K = 64)
    gemm_nn_bias<<<gProj, 256>>>(x, enc_W, enc_b, p_h, BSROWS, DMODEL, INDIM);

    for (int l = 0; l < NL; l++) {
        const size_t wofs = (size_t)l * DMODEL * DMODEL;
        const size_t bofs = (size_t)l * DMODEL;

        gemm_nn_bias<<<gProj, 256>>>(p_h, Wq + wofs, bq + bofs, p_q, BSROWS, DMODEL, DMODEL);
        gemm_nn_bias<<<gProj, 256>>>(p_h, Wk + wofs, bk + bofs, p_k, BSROWS, DMODEL, DMODEL);
        gemm_nn_bias<<<gProj, 256>>>(p_h, Wv + wofs, bv + bofs, p_v, BSROWS, DMODEL, DMODEL);

        qk_scores_kernel<<<dim3(SEQ / 64, SEQ / 64, B_ * NH), 256>>>();
        topk_softmax_kernel<<<B_ * NH * SEQ, 256>>>();
        av_kernel<<<dim3(SEQ / 64, B_ * NH), 256>>>();

        gemm_nn_bias<<<gProj, 256>>>(p_ao, fcW + wofs, fcb + bofs, p_fc, BSROWS, DMODEL, DMODEL);
        add_ln_kernel<<<BSROWS, 256>>>(ln_g + bofs, ln_b + bofs);
    }

    decoder_kernel<<<B_, INDIM>>>(dec_W, dec_b, out);
}